// round 1
// baseline (speedup 1.0000x reference)
#include <cuda_runtime.h>
#include <cstddef>

// ---------------- problem constants ----------------
constexpr int B_   = 4;
constexpr int S_   = 2048;
constexpr int HD_  = 1024;
constexpr int NH_  = 8;
constexpr int DK_  = 128;    // head dim
constexpr int WA_  = 67;     // dwt output width
constexpr int BH_  = B_ * NH_;         // 32
constexpr int OUT1W_ = NH_ * WA_;      // 536

// ---------------- device scratch (static, allocation-free) ----------------
__device__ float g_q [(size_t)BH_ * S_ * DK_];   // (B,H,S,dk), pre-scaled
__device__ float g_k [(size_t)BH_ * S_ * DK_];
__device__ float g_v [(size_t)BH_ * S_ * DK_];
__device__ float g_cD[(size_t)BH_ * S_ * WA_];
__device__ float g_sc[(size_t)BH_ * S_ * S_];    // scores / probs, 512MB

// db4 filters, pre-reversed so out[o] = sum_t e[2o+t]*REV[t]
__constant__ float REV_LO[8] = {
    0.23037781330885523f,  0.7148465705525415f,  0.6308807679295904f,
   -0.02798376941698385f, -0.18703481171888114f, 0.030841381835986965f,
    0.032883011666982945f,-0.010597401784997278f };
__constant__ float REV_HI[8] = {
   -0.010597401784997278f,-0.032883011666982945f, 0.030841381835986965f,
    0.18703481171888114f, -0.02798376941698385f, -0.6308807679295904f,
    0.7148465705525415f,  -0.23037781330885523f };

// =====================================================================
// Kernel 1: QKV projections.  y = x @ W^T  (NT GEMM, both K-major),
// epilogue scatters into (B,H,S,dk) layout; q gets dk^-0.5 scale.
// grid (HD/128, B*S/128, 3), 256 threads
// =====================================================================
__global__ void __launch_bounds__(256, 2)
qkv_gemm(const float* __restrict__ x,
         const float* __restrict__ Wq,
         const float* __restrict__ Wk,
         const float* __restrict__ Wv)
{
    const int mode = blockIdx.z;
    const float* Wm = (mode == 0) ? Wq : (mode == 1) ? Wk : Wv;
    float* dst      = (mode == 0) ? g_q : (mode == 1) ? g_k : g_v;
    const float scale = (mode == 0) ? 0.08838834764831845f : 1.0f;  // 128^-0.5

    __shared__ float As[8][128];
    __shared__ float Bs[8][128];

    const int tid = threadIdx.x;
    const int m0 = blockIdx.y * 128;
    const int n0 = blockIdx.x * 128;
    const int lr = tid >> 1;
    const int lc = (tid & 1) * 4;
    const int tx = tid & 15, ty = tid >> 4;

    float acc[8][8] = {};

    for (int k0 = 0; k0 < HD_; k0 += 8) {
        float4 av = *(const float4*)&x [(size_t)(m0 + lr) * HD_ + k0 + lc];
        float4 bv = *(const float4*)&Wm[(size_t)(n0 + lr) * HD_ + k0 + lc];
        As[lc+0][lr] = av.x; As[lc+1][lr] = av.y; As[lc+2][lr] = av.z; As[lc+3][lr] = av.w;
        Bs[lc+0][lr] = bv.x; Bs[lc+1][lr] = bv.y; Bs[lc+2][lr] = bv.z; Bs[lc+3][lr] = bv.w;
        __syncthreads();
#pragma unroll
        for (int kk = 0; kk < 8; ++kk) {
            float a[8], b[8];
            *(float4*)&a[0] = *(const float4*)&As[kk][ty * 8];
            *(float4*)&a[4] = *(const float4*)&As[kk][ty * 8 + 4];
            *(float4*)&b[0] = *(const float4*)&Bs[kk][tx * 8];
            *(float4*)&b[4] = *(const float4*)&Bs[kk][tx * 8 + 4];
#pragma unroll
            for (int i = 0; i < 8; ++i)
#pragma unroll
                for (int j = 0; j < 8; ++j)
                    acc[i][j] += a[i] * b[j];
        }
        __syncthreads();
    }

#pragma unroll
    for (int i = 0; i < 8; ++i) {
        const int m = m0 + ty * 8 + i;
        const int b = m >> 11, s = m & (S_ - 1);
#pragma unroll
        for (int j = 0; j < 8; ++j) {
            const int n = n0 + tx * 8 + j;
            const int h = n >> 7, d = n & 127;
            dst[((size_t)(b * NH_ + h) * S_ + s) * DK_ + d] = acc[i][j] * scale;
        }
    }
}

// =====================================================================
// Kernel 2: db4 DWT along dk of v. cA -> out2 (raw layout), cD -> g_cD.
// Symmetric half-point extension exactly matching reference.
// grid BH*S blocks, 128 threads
// =====================================================================
__global__ void dwt_kernel(float* __restrict__ out2)
{
    const int row = blockIdx.x;                  // (b*NH+h)*S + s
    const float* vr = g_v + (size_t)row * DK_;
    __shared__ float e[141];
    const int t = threadIdx.x;

    e[t + 6] = vr[t];
    if (t < 6)  e[t]        = vr[5 - t];
    if (t < 7)  e[134 + t]  = vr[127 - t];
    __syncthreads();

    if (t < WA_) {
        float a = 0.f, d = 0.f;
#pragma unroll
        for (int u = 0; u < 8; ++u) {
            const float xv = e[2 * t + u];
            a += xv * REV_LO[u];
            d += xv * REV_HI[u];
        }
        out2[(size_t)row * WA_ + t] = a;
        g_cD[(size_t)row * WA_ + t] = d;
    }
}

// =====================================================================
// Kernel 3: scores = q @ k^T per (b,h).  NT GEMM, M=N=2048, K=128.
// grid (16, 16, BH), 256 threads
// =====================================================================
__global__ void __launch_bounds__(256, 2)
scores_gemm()
{
    const int bh = blockIdx.z;
    const float* A  = g_q + (size_t)bh * S_ * DK_;
    const float* Bp = g_k + (size_t)bh * S_ * DK_;
    float* C = g_sc + (size_t)bh * S_ * S_;

    __shared__ float As[8][128];
    __shared__ float Bs[8][128];

    const int tid = threadIdx.x;
    const int m0 = blockIdx.y * 128;
    const int n0 = blockIdx.x * 128;
    const int lr = tid >> 1;
    const int lc = (tid & 1) * 4;
    const int tx = tid & 15, ty = tid >> 4;

    float acc[8][8] = {};

    for (int k0 = 0; k0 < DK_; k0 += 8) {
        float4 av = *(const float4*)&A [(size_t)(m0 + lr) * DK_ + k0 + lc];
        float4 bv = *(const float4*)&Bp[(size_t)(n0 + lr) * DK_ + k0 + lc];
        As[lc+0][lr] = av.x; As[lc+1][lr] = av.y; As[lc+2][lr] = av.z; As[lc+3][lr] = av.w;
        Bs[lc+0][lr] = bv.x; Bs[lc+1][lr] = bv.y; Bs[lc+2][lr] = bv.z; Bs[lc+3][lr] = bv.w;
        __syncthreads();
#pragma unroll
        for (int kk = 0; kk < 8; ++kk) {
            float a[8], b[8];
            *(float4*)&a[0] = *(const float4*)&As[kk][ty * 8];
            *(float4*)&a[4] = *(const float4*)&As[kk][ty * 8 + 4];
            *(float4*)&b[0] = *(const float4*)&Bs[kk][tx * 8];
            *(float4*)&b[4] = *(const float4*)&Bs[kk][tx * 8 + 4];
#pragma unroll
            for (int i = 0; i < 8; ++i)
#pragma unroll
                for (int j = 0; j < 8; ++j)
                    acc[i][j] += a[i] * b[j];
        }
        __syncthreads();
    }

#pragma unroll
    for (int i = 0; i < 8; ++i) {
        const int m = m0 + ty * 8 + i;
#pragma unroll
        for (int j = 0; j < 8; j += 4) {
            float4 w = make_float4(acc[i][j], acc[i][j+1], acc[i][j+2], acc[i][j+3]);
            *(float4*)&C[(size_t)m * S_ + n0 + tx * 8 + j] = w;
        }
    }
}

// =====================================================================
// Kernel 4: stable softmax over rows of 2048, in place.
// grid BH*S blocks, 256 threads (8 elems/thread)
// =====================================================================
__global__ void softmax_kernel()
{
    float* row = g_sc + (size_t)blockIdx.x * S_;
    const int t = threadIdx.x;

    float4 v0 = ((const float4*)row)[t * 2];
    float4 v1 = ((const float4*)row)[t * 2 + 1];

    float mx = fmaxf(fmaxf(fmaxf(v0.x, v0.y), fmaxf(v0.z, v0.w)),
                     fmaxf(fmaxf(v1.x, v1.y), fmaxf(v1.z, v1.w)));

    __shared__ float sred[256];
    sred[t] = mx; __syncthreads();
    for (int o = 128; o > 0; o >>= 1) {
        if (t < o) sred[t] = fmaxf(sred[t], sred[t + o]);
        __syncthreads();
    }
    const float rm = sred[0];
    __syncthreads();

    v0.x = __expf(v0.x - rm); v0.y = __expf(v0.y - rm);
    v0.z = __expf(v0.z - rm); v0.w = __expf(v0.w - rm);
    v1.x = __expf(v1.x - rm); v1.y = __expf(v1.y - rm);
    v1.z = __expf(v1.z - rm); v1.w = __expf(v1.w - rm);

    float ps = v0.x + v0.y + v0.z + v0.w + v1.x + v1.y + v1.z + v1.w;
    sred[t] = ps; __syncthreads();
    for (int o = 128; o > 0; o >>= 1) {
        if (t < o) sred[t] += sred[t + o];
        __syncthreads();
    }
    const float inv = 1.0f / sred[0];

    v0.x *= inv; v0.y *= inv; v0.z *= inv; v0.w *= inv;
    v1.x *= inv; v1.y *= inv; v1.z *= inv; v1.w *= inv;
    ((float4*)row)[t * 2]     = v0;
    ((float4*)row)[t * 2 + 1] = v1;
}

// =====================================================================
// Kernel 5: out1 = P @ cD per (b,h).  NN GEMM M=2048, N=67 (pad 128), K=2048.
// Epilogue writes directly into out1 (B,S,H*WA) layout.
// grid (1, 16, BH), 256 threads
// =====================================================================
__global__ void __launch_bounds__(256, 2)
pcd_gemm(float* __restrict__ out1)
{
    const int bh = blockIdx.z;
    const int b = bh >> 3, h = bh & 7;
    const float* A   = g_sc + (size_t)bh * S_ * S_;
    const float* Bcd = g_cD + (size_t)bh * S_ * WA_;

    __shared__ float As[8][128];
    __shared__ float Bs[8][128];

    const int tid = threadIdx.x;
    const int m0 = blockIdx.y * 128;
    const int lr = tid >> 1;
    const int lc = (tid & 1) * 4;
    const int tx = tid & 15, ty = tid >> 4;

    float acc[8][8] = {};

    for (int k0 = 0; k0 < S_; k0 += 8) {
        float4 av = *(const float4*)&A[(size_t)(m0 + lr) * S_ + k0 + lc];
        As[lc+0][lr] = av.x; As[lc+1][lr] = av.y; As[lc+2][lr] = av.z; As[lc+3][lr] = av.w;
#pragma unroll
        for (int i2 = 0; i2 < 4; ++i2) {
            const int e  = tid * 4 + i2;
            const int kk = e >> 7, nn = e & 127;
            Bs[kk][nn] = (nn < WA_) ? Bcd[(size_t)(k0 + kk) * WA_ + nn] : 0.f;
        }
        __syncthreads();
#pragma unroll
        for (int kk = 0; kk < 8; ++kk) {
            float a[8], bb[8];
            *(float4*)&a[0]  = *(const float4*)&As[kk][ty * 8];
            *(float4*)&a[4]  = *(const float4*)&As[kk][ty * 8 + 4];
            *(float4*)&bb[0] = *(const float4*)&Bs[kk][tx * 8];
            *(float4*)&bb[4] = *(const float4*)&Bs[kk][tx * 8 + 4];
#pragma unroll
            for (int i = 0; i < 8; ++i)
#pragma unroll
                for (int j = 0; j < 8; ++j)
                    acc[i][j] += a[i] * bb[j];
        }
        __syncthreads();
    }

#pragma unroll
    for (int i = 0; i < 8; ++i) {
        const int s = m0 + ty * 8 + i;
#pragma unroll
        for (int j = 0; j < 8; ++j) {
            const int n = tx * 8 + j;
            if (n < WA_)
                out1[((size_t)(b * S_ + s)) * OUT1W_ + h * WA_ + n] = acc[i][j];
        }
    }
}

// =====================================================================
extern "C" void kernel_launch(void* const* d_in, const int* in_sizes, int n_in,
                              void* d_out, int out_size)
{
    const float* x  = (const float*)d_in[0];
    const float* Wq = (const float*)d_in[1];
    const float* Wk = (const float*)d_in[2];
    const float* Wv = (const float*)d_in[3];

    float* out1 = (float*)d_out;
    float* out2 = out1 + (size_t)out_size / 2;   // out2 = cA raw (B,H,S,WA)

    qkv_gemm   <<<dim3(HD_ / 128, (B_ * S_) / 128, 3), 256>>>(x, Wq, Wk, Wv);
    dwt_kernel <<<BH_ * S_, 128>>>(out2);
    scores_gemm<<<dim3(S_ / 128, S_ / 128, BH_), 256>>>();
    softmax_kernel<<<BH_ * S_, 256>>>();
    pcd_gemm   <<<dim3(1, S_ / 128, BH_), 256>>>(out1);
}

// round 3
// speedup vs baseline: 1.9221x; 1.9221x over previous
#include <cuda_runtime.h>
#include <cstdint>
#include <cstddef>

// ---------------- problem constants ----------------
constexpr int B_   = 4;
constexpr int S_   = 2048;
constexpr int HD_  = 1024;
constexpr int NH_  = 8;
constexpr int DK_  = 128;
constexpr int WA_  = 67;
constexpr int BH_  = B_ * NH_;         // 32
constexpr int OUT1W_ = NH_ * WA_;      // 536
constexpr int LDT  = 36;               // smem tile stride in floats (conflict-free frags)

// ---------------- device scratch ----------------
__device__ float g_q  [(size_t)BH_ * S_ * DK_];
__device__ float g_k  [(size_t)BH_ * S_ * DK_];
__device__ float g_v  [(size_t)BH_ * S_ * DK_];
__device__ float g_cDT[(size_t)BH_ * WA_ * S_];   // transposed cD: [bh][wa][s]
__device__ float g_sc [(size_t)BH_ * S_ * S_];    // raw logits, 512MB
__device__ float g_rmax[(size_t)BH_ * S_];
__device__ float g_rinv[(size_t)BH_ * S_];

__constant__ float REV_LO[8] = {
    0.23037781330885523f,  0.7148465705525415f,  0.6308807679295904f,
   -0.02798376941698385f, -0.18703481171888114f, 0.030841381835986965f,
    0.032883011666982945f,-0.010597401784997278f };
__constant__ float REV_HI[8] = {
   -0.010597401784997278f,-0.032883011666982945f, 0.030841381835986965f,
    0.18703481171888114f, -0.02798376941698385f, -0.6308807679295904f,
    0.7148465705525415f,  -0.23037781330885523f };

// ---------------- helpers ----------------
static __device__ __forceinline__ float tf32r(float x) {
    uint32_t u; asm("cvt.rna.tf32.f32 %0, %1;" : "=r"(u) : "f"(x));
    return __uint_as_float(u);
}
static __device__ __forceinline__ float4 tf32r4(float4 v) {
    v.x = tf32r(v.x); v.y = tf32r(v.y); v.z = tf32r(v.z); v.w = tf32r(v.w);
    return v;
}
// m16n8k8 tf32 mma (A row-major, B col-major), D += A*B
static __device__ __forceinline__ void mma8(float* c,
    float a0, float a1, float a2, float a3, float b0, float b1)
{
    asm volatile(
        "mma.sync.aligned.m16n8k8.row.col.f32.tf32.tf32.f32 "
        "{%0,%1,%2,%3},{%4,%5,%6,%7},{%8,%9},{%0,%1,%2,%3};"
        : "+f"(c[0]), "+f"(c[1]), "+f"(c[2]), "+f"(c[3])
        : "r"(__float_as_uint(a0)), "r"(__float_as_uint(a1)),
          "r"(__float_as_uint(a2)), "r"(__float_as_uint(a3)),
          "r"(__float_as_uint(b0)), "r"(__float_as_uint(b1)));
}

constexpr size_t SMEM_QKV    = (size_t)(128 * LDT + 64 * LDT) * 4;        // 27648
constexpr size_t SMEM_SCORES = (size_t)2 * (128 * LDT + 64 * LDT) * 4;    // 55296
constexpr size_t SMEM_PCD    = SMEM_QKV;

// =====================================================================
// Kernel 1: QKV, y = x @ W^T.  block 128x64, warps 4x2, warp tile 32x32
// grid (HD/64, 8192/128, 3)
// =====================================================================
__global__ void __launch_bounds__(256, 2)
qkv_gemm(const float* __restrict__ x, const float* __restrict__ Wq,
         const float* __restrict__ Wk, const float* __restrict__ Wv)
{
    extern __shared__ float sm[];
    float* As = sm;                 // 128 x LDT
    float* Bs = sm + 128 * LDT;     // 64 x LDT

    const int mode = blockIdx.z;
    const float* Wm = (mode == 0) ? Wq : (mode == 1) ? Wk : Wv;
    float* dst      = (mode == 0) ? g_q : (mode == 1) ? g_k : g_v;
    const float scale = (mode == 0) ? 0.08838834764831845f : 1.0f;

    const int tid = threadIdx.x;
    const int m0 = blockIdx.y * 128, n0 = blockIdx.x * 64;
    const int arow = tid >> 1, acol = (tid & 1) * 16;
    const int brow = tid >> 2, bcol = (tid & 3) * 8;
    const float* ag = x  + (size_t)(m0 + arow) * HD_ + acol;
    const float* bg = Wm + (size_t)(n0 + brow) * HD_ + bcol;

    const int lane = tid & 31, wid = tid >> 5;
    const int wm = wid >> 1, wn = wid & 1, grp = lane >> 2, q4 = lane & 3;
    const int abase = (wm * 32 + grp) * LDT + q4;
    const int bbase = (wn * 32 + grp) * LDT + q4;

    float acc[2][4][4] = {};
    float4 rA[4], rB[2];

#pragma unroll
    for (int i = 0; i < 4; ++i) rA[i] = *(const float4*)(ag + i * 4);
#pragma unroll
    for (int i = 0; i < 2; ++i) rB[i] = *(const float4*)(bg + i * 4);

    for (int kc = 0; kc < HD_ / 32; ++kc) {
        __syncthreads();
#pragma unroll
        for (int i = 0; i < 4; ++i)
            *(float4*)&As[arow * LDT + acol + i * 4] = tf32r4(rA[i]);
#pragma unroll
        for (int i = 0; i < 2; ++i)
            *(float4*)&Bs[brow * LDT + bcol + i * 4] = tf32r4(rB[i]);
        __syncthreads();
        if (kc + 1 < HD_ / 32) {
#pragma unroll
            for (int i = 0; i < 4; ++i) rA[i] = *(const float4*)(ag + (kc + 1) * 32 + i * 4);
#pragma unroll
            for (int i = 0; i < 2; ++i) rB[i] = *(const float4*)(bg + (kc + 1) * 32 + i * 4);
        }
#pragma unroll
        for (int k8 = 0; k8 < 32; k8 += 8) {
            float a[2][4], b[4][2];
#pragma unroll
            for (int i = 0; i < 2; ++i) {
                const int o = abase + i * 16 * LDT + k8;
                a[i][0] = As[o];            a[i][1] = As[o + 8 * LDT];
                a[i][2] = As[o + 4];        a[i][3] = As[o + 8 * LDT + 4];
            }
#pragma unroll
            for (int j = 0; j < 4; ++j) {
                const int o = bbase + j * 8 * LDT + k8;
                b[j][0] = Bs[o];            b[j][1] = Bs[o + 4];
            }
#pragma unroll
            for (int i = 0; i < 2; ++i)
#pragma unroll
                for (int j = 0; j < 4; ++j)
                    mma8(acc[i][j], a[i][0], a[i][1], a[i][2], a[i][3], b[j][0], b[j][1]);
        }
    }

#pragma unroll
    for (int i = 0; i < 2; ++i) {
#pragma unroll
        for (int r = 0; r < 2; ++r) {
            const int m = m0 + wm * 32 + i * 16 + grp + r * 8;
            const int bb = m >> 11, s = m & (S_ - 1);
#pragma unroll
            for (int j = 0; j < 4; ++j) {
                const int n = n0 + wn * 32 + j * 8 + 2 * q4;
                const int h = n >> 7, d = n & 127;
                float2 w = make_float2(acc[i][j][2 * r] * scale, acc[i][j][2 * r + 1] * scale);
                *(float2*)&dst[((size_t)(bb * NH_ + h) * S_ + s) * DK_ + d] = w;
            }
        }
    }
}

// =====================================================================
// Kernel 2: db4 DWT of v. cA -> out2 (raw), cD -> g_cDT (transposed).
// =====================================================================
__global__ void dwt_kernel(float* __restrict__ out2)
{
    const int rowi = blockIdx.x;                 // bh*S + s
    const float* vr = g_v + (size_t)rowi * DK_;
    __shared__ float e[141];
    const int t = threadIdx.x;

    e[t + 6] = vr[t];
    if (t < 6)  e[t]       = vr[5 - t];
    if (t < 7)  e[134 + t] = vr[127 - t];
    __syncthreads();

    if (t < WA_) {
        float a = 0.f, d = 0.f;
#pragma unroll
        for (int u = 0; u < 8; ++u) {
            const float xv = e[2 * t + u];
            a += xv * REV_LO[u];
            d += xv * REV_HI[u];
        }
        out2[(size_t)rowi * WA_ + t] = a;
        const int bh = rowi >> 11, s = rowi & (S_ - 1);
        g_cDT[((size_t)bh * WA_ + t) * S_ + s] = d;
    }
}

// =====================================================================
// Kernel 3: scores = q @ k^T, split-tf32 (hi/lo, 3 mma per tile-step).
// block 128x64, grid (2048/64, 2048/128, 32).  K=128, 4 chunks.
// =====================================================================
__global__ void __launch_bounds__(256, 2)
scores_gemm()
{
    extern __shared__ float sm[];
    float* Ah = sm;
    float* Al = Ah + 128 * LDT;
    float* Bh = Al + 128 * LDT;
    float* Bl = Bh + 64 * LDT;

    const int bh = blockIdx.z;
    const int tid = threadIdx.x;
    const int m0 = blockIdx.y * 128, n0 = blockIdx.x * 64;
    const int arow = tid >> 1, acol = (tid & 1) * 16;
    const int brow = tid >> 2, bcol = (tid & 3) * 8;
    const float* ag = g_q + (size_t)bh * S_ * DK_ + (size_t)(m0 + arow) * DK_ + acol;
    const float* bg = g_k + (size_t)bh * S_ * DK_ + (size_t)(n0 + brow) * DK_ + bcol;

    const int lane = tid & 31, wid = tid >> 5;
    const int wm = wid >> 1, wn = wid & 1, grp = lane >> 2, q4 = lane & 3;
    const int abase = (wm * 32 + grp) * LDT + q4;
    const int bbase = (wn * 32 + grp) * LDT + q4;

    float acc[2][4][4] = {};
    float4 rA[4], rB[2];

#pragma unroll
    for (int i = 0; i < 4; ++i) rA[i] = *(const float4*)(ag + i * 4);
#pragma unroll
    for (int i = 0; i < 2; ++i) rB[i] = *(const float4*)(bg + i * 4);

    for (int kc = 0; kc < DK_ / 32; ++kc) {
        __syncthreads();
#pragma unroll
        for (int i = 0; i < 4; ++i) {
            float4 h = tf32r4(rA[i]);
            float4 l; l.x = tf32r(rA[i].x - h.x); l.y = tf32r(rA[i].y - h.y);
                      l.z = tf32r(rA[i].z - h.z); l.w = tf32r(rA[i].w - h.w);
            *(float4*)&Ah[arow * LDT + acol + i * 4] = h;
            *(float4*)&Al[arow * LDT + acol + i * 4] = l;
        }
#pragma unroll
        for (int i = 0; i < 2; ++i) {
            float4 h = tf32r4(rB[i]);
            float4 l; l.x = tf32r(rB[i].x - h.x); l.y = tf32r(rB[i].y - h.y);
                      l.z = tf32r(rB[i].z - h.z); l.w = tf32r(rB[i].w - h.w);
            *(float4*)&Bh[brow * LDT + bcol + i * 4] = h;
            *(float4*)&Bl[brow * LDT + bcol + i * 4] = l;
        }
        __syncthreads();
        if (kc + 1 < DK_ / 32) {
#pragma unroll
            for (int i = 0; i < 4; ++i) rA[i] = *(const float4*)(ag + (kc + 1) * 32 + i * 4);
#pragma unroll
            for (int i = 0; i < 2; ++i) rB[i] = *(const float4*)(bg + (kc + 1) * 32 + i * 4);
        }
#pragma unroll
        for (int k8 = 0; k8 < 32; k8 += 8) {
            float ah[2][4], bhf[4][2];
#pragma unroll
            for (int i = 0; i < 2; ++i) {
                const int o = abase + i * 16 * LDT + k8;
                ah[i][0] = Ah[o];     ah[i][1] = Ah[o + 8 * LDT];
                ah[i][2] = Ah[o + 4]; ah[i][3] = Ah[o + 8 * LDT + 4];
            }
#pragma unroll
            for (int j = 0; j < 4; ++j) {
                const int o = bbase + j * 8 * LDT + k8;
                bhf[j][0] = Bh[o]; bhf[j][1] = Bh[o + 4];
            }
            // hi * hi
#pragma unroll
            for (int i = 0; i < 2; ++i)
#pragma unroll
                for (int j = 0; j < 4; ++j)
                    mma8(acc[i][j], ah[i][0], ah[i][1], ah[i][2], ah[i][3], bhf[j][0], bhf[j][1]);
            // hi * lo
#pragma unroll
            for (int j = 0; j < 4; ++j) {
                const int o = bbase + j * 8 * LDT + k8;
                float b0 = Bl[o], b1 = Bl[o + 4];
#pragma unroll
                for (int i = 0; i < 2; ++i)
                    mma8(acc[i][j], ah[i][0], ah[i][1], ah[i][2], ah[i][3], b0, b1);
            }
            // lo * hi
#pragma unroll
            for (int i = 0; i < 2; ++i) {
                const int o = abase + i * 16 * LDT + k8;
                float a0 = Al[o], a1 = Al[o + 8 * LDT], a2 = Al[o + 4], a3 = Al[o + 8 * LDT + 4];
#pragma unroll
                for (int j = 0; j < 4; ++j)
                    mma8(acc[i][j], a0, a1, a2, a3, bhf[j][0], bhf[j][1]);
            }
        }
    }

#pragma unroll
    for (int i = 0; i < 2; ++i) {
#pragma unroll
        for (int r = 0; r < 2; ++r) {
            const int m = m0 + wm * 32 + i * 16 + grp + r * 8;
            float* crow = g_sc + ((size_t)bh * S_ + m) * S_;
#pragma unroll
            for (int j = 0; j < 4; ++j) {
                const int n = n0 + wn * 32 + j * 8 + 2 * q4;
                *(float2*)&crow[n] = make_float2(acc[i][j][2 * r], acc[i][j][2 * r + 1]);
            }
        }
    }
}

// =====================================================================
// Kernel 4: per-row max and 1/sum(exp) of logits.
// =====================================================================
__global__ void rowstat_kernel()
{
    const size_t r = blockIdx.x;
    const float* row = g_sc + r * S_;
    const int t = threadIdx.x;

    float4 v0 = ((const float4*)row)[t * 2];
    float4 v1 = ((const float4*)row)[t * 2 + 1];
    float mx = fmaxf(fmaxf(fmaxf(v0.x, v0.y), fmaxf(v0.z, v0.w)),
                     fmaxf(fmaxf(v1.x, v1.y), fmaxf(v1.z, v1.w)));

    __shared__ float sred[256];
    sred[t] = mx; __syncthreads();
    for (int o = 128; o > 0; o >>= 1) {
        if (t < o) sred[t] = fmaxf(sred[t], sred[t + o]);
        __syncthreads();
    }
    const float rm = sred[0];
    __syncthreads();

    float ps = __expf(v0.x - rm) + __expf(v0.y - rm) + __expf(v0.z - rm) +
               __expf(v0.w - rm) + __expf(v1.x - rm) + __expf(v1.y - rm) +
               __expf(v1.z - rm) + __expf(v1.w - rm);
    sred[t] = ps; __syncthreads();
    for (int o = 128; o > 0; o >>= 1) {
        if (t < o) sred[t] += sred[t + o];
        __syncthreads();
    }
    if (t == 0) { g_rmax[r] = rm; g_rinv[r] = 1.0f / sred[0]; }
}

// =====================================================================
// Kernel 5: out1 = softmax(logits) @ cD^T-view.  exp fused into A stage.
// block 128x64, grid (2, 16, 32).  K = 2048, 64 chunks.
// =====================================================================
__global__ void __launch_bounds__(256, 2)
pcd_gemm(float* __restrict__ out1)
{
    extern __shared__ float sm[];
    float* As = sm;
    float* Bs = sm + 128 * LDT;

    const int bh = blockIdx.z;
    const int bb = bh >> 3, hh = bh & 7;
    const int tid = threadIdx.x;
    const int m0 = blockIdx.y * 128, n0 = blockIdx.x * 64;
    const int arow = tid >> 1, acol = (tid & 1) * 16;
    const int brow = tid >> 2, bcol = (tid & 3) * 8;

    const float rm = g_rmax[(size_t)bh * S_ + m0 + arow];
    const float ri = g_rinv[(size_t)bh * S_ + m0 + arow];

    const float* ag = g_sc + ((size_t)bh * S_ + m0 + arow) * S_ + acol;
    const int nglob = n0 + brow;
    const bool balive = (nglob < WA_);
    const float* bg = g_cDT + ((size_t)bh * WA_ + nglob) * S_ + bcol;

    const int lane = tid & 31, wid = tid >> 5;
    const int wm = wid >> 1, wn = wid & 1, grp = lane >> 2, q4 = lane & 3;
    const int abase = (wm * 32 + grp) * LDT + q4;
    const int bbase = (wn * 32 + grp) * LDT + q4;

    float acc[2][4][4] = {};
    float4 rA[4], rB[2];
    const float4 z4 = make_float4(0.f, 0.f, 0.f, 0.f);

#pragma unroll
    for (int i = 0; i < 4; ++i) rA[i] = *(const float4*)(ag + i * 4);
#pragma unroll
    for (int i = 0; i < 2; ++i) rB[i] = balive ? *(const float4*)(bg + i * 4) : z4;

    for (int kc = 0; kc < S_ / 32; ++kc) {
        __syncthreads();
#pragma unroll
        for (int i = 0; i < 4; ++i) {
            float4 v = rA[i];
            v.x = tf32r(__expf(v.x - rm) * ri);
            v.y = tf32r(__expf(v.y - rm) * ri);
            v.z = tf32r(__expf(v.z - rm) * ri);
            v.w = tf32r(__expf(v.w - rm) * ri);
            *(float4*)&As[arow * LDT + acol + i * 4] = v;
        }
#pragma unroll
        for (int i = 0; i < 2; ++i)
            *(float4*)&Bs[brow * LDT + bcol + i * 4] = tf32r4(rB[i]);
        __syncthreads();
        if (kc + 1 < S_ / 32) {
#pragma unroll
            for (int i = 0; i < 4; ++i) rA[i] = *(const float4*)(ag + (kc + 1) * 32 + i * 4);
#pragma unroll
            for (int i = 0; i < 2; ++i) rB[i] = balive ? *(const float4*)(bg + (kc + 1) * 32 + i * 4) : z4;
        }
#pragma unroll
        for (int k8 = 0; k8 < 32; k8 += 8) {
            float a[2][4], b[4][2];
#pragma unroll
            for (int i = 0; i < 2; ++i) {
                const int o = abase + i * 16 * LDT + k8;
                a[i][0] = As[o];     a[i][1] = As[o + 8 * LDT];
                a[i][2] = As[o + 4]; a[i][3] = As[o + 8 * LDT + 4];
            }
#pragma unroll
            for (int j = 0; j < 4; ++j) {
                const int o = bbase + j * 8 * LDT + k8;
                b[j][0] = Bs[o]; b[j][1] = Bs[o + 4];
            }
#pragma unroll
            for (int i = 0; i < 2; ++i)
#pragma unroll
                for (int j = 0; j < 4; ++j)
                    mma8(acc[i][j], a[i][0], a[i][1], a[i][2], a[i][3], b[j][0], b[j][1]);
        }
    }

#pragma unroll
    for (int i = 0; i < 2; ++i) {
#pragma unroll
        for (int r = 0; r < 2; ++r) {
            const int s = m0 + wm * 32 + i * 16 + grp + r * 8;
            float* orow = out1 + (size_t)(bb * S_ + s) * OUT1W_ + hh * WA_;
#pragma unroll
            for (int j = 0; j < 4; ++j) {
                const int n = n0 + wn * 32 + j * 8 + 2 * q4;
                if (n < WA_)     orow[n]     = acc[i][j][2 * r];
                if (n + 1 < WA_) orow[n + 1] = acc[i][j][2 * r + 1];
            }
        }
    }
}

// =====================================================================
extern "C" void kernel_launch(void* const* d_in, const int* in_sizes, int n_in,
                              void* d_out, int out_size)
{
    const float* x  = (const float*)d_in[0];
    const float* Wq = (const float*)d_in[1];
    const float* Wk = (const float*)d_in[2];
    const float* Wv = (const float*)d_in[3];

    float* out1 = (float*)d_out;
    float* out2 = out1 + (size_t)out_size / 2;

    cudaFuncSetAttribute(qkv_gemm,    cudaFuncAttributeMaxDynamicSharedMemorySize, (int)SMEM_QKV);
    cudaFuncSetAttribute(scores_gemm, cudaFuncAttributeMaxDynamicSharedMemorySize, (int)SMEM_SCORES);
    cudaFuncSetAttribute(pcd_gemm,    cudaFuncAttributeMaxDynamicSharedMemorySize, (int)SMEM_PCD);

    qkv_gemm   <<<dim3(HD_ / 64, (B_ * S_) / 128, 3), 256, SMEM_QKV>>>(x, Wq, Wk, Wv);
    dwt_kernel <<<BH_ * S_, 128>>>(out2);
    scores_gemm<<<dim3(S_ / 64, S_ / 128, BH_), 256, SMEM_SCORES>>>();
    rowstat_kernel<<<BH_ * S_, 256>>>();
    pcd_gemm   <<<dim3(2, S_ / 128, BH_), 256, SMEM_PCD>>>(out1);
}

// round 4
// speedup vs baseline: 2.5394x; 1.3212x over previous
#include <cuda_runtime.h>
#include <cstdint>
#include <cstddef>
#include <math_constants.h>

// ---------------- problem constants ----------------
constexpr int B_   = 4;
constexpr int S_   = 2048;
constexpr int HD_  = 1024;
constexpr int NH_  = 8;
constexpr int DK_  = 128;
constexpr int WA_  = 67;
constexpr int BH_  = B_ * NH_;         // 32
constexpr int OUT1W_ = NH_ * WA_;      // 536
constexpr int LDT  = 36;               // qkv smem stride (conflict-free frags)

// fused-kernel geometry
constexpr int KT   = 64;               // seq cols per k-tile
constexpr int QLD  = 132;              // Q/K smem stride
constexpr int CLD  = 68;               // cD / P smem stride
constexpr int NP   = 72;               // padded wavelet rows (9 n8 tiles)

// ---------------- device scratch ----------------
__device__ float g_q  [(size_t)BH_ * S_ * DK_];
__device__ float g_k  [(size_t)BH_ * S_ * DK_];
__device__ float g_v  [(size_t)BH_ * S_ * DK_];
__device__ float g_cDT[(size_t)BH_ * WA_ * S_];   // transposed cD: [bh][wa][s]

__constant__ float REV_LO[8] = {
    0.23037781330885523f,  0.7148465705525415f,  0.6308807679295904f,
   -0.02798376941698385f, -0.18703481171888114f, 0.030841381835986965f,
    0.032883011666982945f,-0.010597401784997278f };
__constant__ float REV_HI[8] = {
   -0.010597401784997278f,-0.032883011666982945f, 0.030841381835986965f,
    0.18703481171888114f, -0.02798376941698385f, -0.6308807679295904f,
    0.7148465705525415f,  -0.23037781330885523f };

// ---------------- helpers ----------------
static __device__ __forceinline__ float tf32r(float x) {
    uint32_t u; asm("cvt.rna.tf32.f32 %0, %1;" : "=r"(u) : "f"(x));
    return __uint_as_float(u);
}
static __device__ __forceinline__ float4 tf32r4(float4 v) {
    v.x = tf32r(v.x); v.y = tf32r(v.y); v.z = tf32r(v.z); v.w = tf32r(v.w);
    return v;
}
static __device__ __forceinline__ void mma8(float* c,
    float a0, float a1, float a2, float a3, float b0, float b1)
{
    asm volatile(
        "mma.sync.aligned.m16n8k8.row.col.f32.tf32.tf32.f32 "
        "{%0,%1,%2,%3},{%4,%5,%6,%7},{%8,%9},{%0,%1,%2,%3};"
        : "+f"(c[0]), "+f"(c[1]), "+f"(c[2]), "+f"(c[3])
        : "r"(__float_as_uint(a0)), "r"(__float_as_uint(a1)),
          "r"(__float_as_uint(a2)), "r"(__float_as_uint(a3)),
          "r"(__float_as_uint(b0)), "r"(__float_as_uint(b1)));
}

constexpr size_t SMEM_QKV = (size_t)(128 * LDT + 64 * LDT) * 4;
constexpr size_t SMEM_FUSED =
    (size_t)(128 * QLD + 2 * KT * QLD + NP * CLD + 8 * 16 * CLD) * 4; // 189568

// =====================================================================
// Kernel 1: QKV, y = x @ W^T.  block 128x64, warps 4x2, warp tile 32x32
// =====================================================================
__global__ void __launch_bounds__(256, 2)
qkv_gemm(const float* __restrict__ x, const float* __restrict__ Wq,
         const float* __restrict__ Wk, const float* __restrict__ Wv)
{
    extern __shared__ float sm[];
    float* As = sm;
    float* Bs = sm + 128 * LDT;

    const int mode = blockIdx.z;
    const float* Wm = (mode == 0) ? Wq : (mode == 1) ? Wk : Wv;
    float* dst      = (mode == 0) ? g_q : (mode == 1) ? g_k : g_v;
    const float scale = (mode == 0) ? 0.08838834764831845f : 1.0f;

    const int tid = threadIdx.x;
    const int m0 = blockIdx.y * 128, n0 = blockIdx.x * 64;
    const int arow = tid >> 1, acol = (tid & 1) * 16;
    const int brow = tid >> 2, bcol = (tid & 3) * 8;
    const float* ag = x  + (size_t)(m0 + arow) * HD_ + acol;
    const float* bg = Wm + (size_t)(n0 + brow) * HD_ + bcol;

    const int lane = tid & 31, wid = tid >> 5;
    const int wm = wid >> 1, wn = wid & 1, grp = lane >> 2, q4 = lane & 3;
    const int abase = (wm * 32 + grp) * LDT + q4;
    const int bbase = (wn * 32 + grp) * LDT + q4;

    float acc[2][4][4] = {};
    float4 rA[4], rB[2];

#pragma unroll
    for (int i = 0; i < 4; ++i) rA[i] = *(const float4*)(ag + i * 4);
#pragma unroll
    for (int i = 0; i < 2; ++i) rB[i] = *(const float4*)(bg + i * 4);

    for (int kc = 0; kc < HD_ / 32; ++kc) {
        __syncthreads();
#pragma unroll
        for (int i = 0; i < 4; ++i)
            *(float4*)&As[arow * LDT + acol + i * 4] = tf32r4(rA[i]);
#pragma unroll
        for (int i = 0; i < 2; ++i)
            *(float4*)&Bs[brow * LDT + bcol + i * 4] = tf32r4(rB[i]);
        __syncthreads();
        if (kc + 1 < HD_ / 32) {
#pragma unroll
            for (int i = 0; i < 4; ++i) rA[i] = *(const float4*)(ag + (kc + 1) * 32 + i * 4);
#pragma unroll
            for (int i = 0; i < 2; ++i) rB[i] = *(const float4*)(bg + (kc + 1) * 32 + i * 4);
        }
#pragma unroll
        for (int k8 = 0; k8 < 32; k8 += 8) {
            float a[2][4], b[4][2];
#pragma unroll
            for (int i = 0; i < 2; ++i) {
                const int o = abase + i * 16 * LDT + k8;
                a[i][0] = As[o];     a[i][1] = As[o + 8 * LDT];
                a[i][2] = As[o + 4]; a[i][3] = As[o + 8 * LDT + 4];
            }
#pragma unroll
            for (int j = 0; j < 4; ++j) {
                const int o = bbase + j * 8 * LDT + k8;
                b[j][0] = Bs[o]; b[j][1] = Bs[o + 4];
            }
#pragma unroll
            for (int i = 0; i < 2; ++i)
#pragma unroll
                for (int j = 0; j < 4; ++j)
                    mma8(acc[i][j], a[i][0], a[i][1], a[i][2], a[i][3], b[j][0], b[j][1]);
        }
    }

#pragma unroll
    for (int i = 0; i < 2; ++i) {
#pragma unroll
        for (int r = 0; r < 2; ++r) {
            const int m = m0 + wm * 32 + i * 16 + grp + r * 8;
            const int bb = m >> 11, s = m & (S_ - 1);
#pragma unroll
            for (int j = 0; j < 4; ++j) {
                const int n = n0 + wn * 32 + j * 8 + 2 * q4;
                const int h = n >> 7, d = n & 127;
                float2 w = make_float2(acc[i][j][2 * r] * scale, acc[i][j][2 * r + 1] * scale);
                *(float2*)&dst[((size_t)(bb * NH_ + h) * S_ + s) * DK_ + d] = w;
            }
        }
    }
}

// =====================================================================
// Kernel 2: db4 DWT of v. cA -> out2 (raw), cD -> g_cDT (transposed).
// =====================================================================
__global__ void dwt_kernel(float* __restrict__ out2)
{
    const int rowi = blockIdx.x;
    const float* vr = g_v + (size_t)rowi * DK_;
    __shared__ float e[141];
    const int t = threadIdx.x;

    e[t + 6] = vr[t];
    if (t < 6)  e[t]       = vr[5 - t];
    if (t < 7)  e[134 + t] = vr[127 - t];
    __syncthreads();

    if (t < WA_) {
        float a = 0.f, d = 0.f;
#pragma unroll
        for (int u = 0; u < 8; ++u) {
            const float xv = e[2 * t + u];
            a += xv * REV_LO[u];
            d += xv * REV_HI[u];
        }
        out2[(size_t)rowi * WA_ + t] = a;
        const int bh = rowi >> 11, s = rowi & (S_ - 1);
        g_cDT[((size_t)bh * WA_ + t) * S_ + s] = d;
    }
}

// =====================================================================
// Kernel 3: FUSED attention: S = split-tf32 q@k^T, online softmax,
// O += P @ cD^T.  grid (16, 32), 256 threads, ~185KB smem, occ 1.
// Each warp owns 16 full q-rows -> warp-local softmax, warp-private P.
// =====================================================================
__global__ void __launch_bounds__(256, 1)
fused_attn(float* __restrict__ out1)
{
    extern __shared__ float sm[];
    float* Qs  = sm;                              // 128 x QLD
    float* Kh  = Qs + 128 * QLD;                  // KT x QLD
    float* Kl  = Kh + KT * QLD;
    float* CDs = Kl + KT * QLD;                   // NP x CLD
    float* Ps  = CDs + NP * CLD;                  // 8 warps x 16 x CLD

    const int bh = blockIdx.y;
    const int q0 = blockIdx.x * 128;
    const int tid = threadIdx.x, lane = tid & 31, wid = tid >> 5;
    const int grp = lane >> 2, q4 = lane & 3;
    float* Pw = Ps + wid * (16 * CLD);

    // ---- Q tile load (128 x 128 fp32) ----
    {
        const int c = (tid & 31) * 4;
#pragma unroll
        for (int p = 0; p < 16; ++p) {
            const int r = (tid >> 5) + p * 8;
            *(float4*)&Qs[r * QLD + c] =
                *(const float4*)(g_q + ((size_t)bh * S_ + q0 + r) * DK_ + c);
        }
    }

    const int kcol = (tid & 31) * 4;   // dk index for K loads
    const int ccol = (tid & 15) * 4;   // seq-in-tile index for cD loads
    float4 kreg[8], creg[5];
#pragma unroll
    for (int p = 0; p < 8; ++p) {
        const int r = (tid >> 5) + p * 8;
        kreg[p] = *(const float4*)(g_k + ((size_t)bh * S_ + r) * DK_ + kcol);
    }
#pragma unroll
    for (int it = 0; it < 5; ++it) {
        const int n = (tid >> 4) + it * 16;
        creg[it] = (n < WA_) ? *(const float4*)(g_cDT + ((size_t)bh * WA_ + n) * S_ + ccol)
                             : make_float4(0.f, 0.f, 0.f, 0.f);
    }

    float oacc[9][4] = {};
    float m0v = -CUDART_INF_F, m1v = -CUDART_INF_F;
    float l0 = 0.f, l1 = 0.f;
    const int arow = wid * 16 + grp;

    for (int kc = 0; kc < S_ / KT; ++kc) {
        __syncthreads();   // previous iteration's reads done
        // store K-tile with hi/lo split
#pragma unroll
        for (int p = 0; p < 8; ++p) {
            const int r = (tid >> 5) + p * 8;
            float4 v = kreg[p];
            float4 h = tf32r4(v);
            float4 l = make_float4(tf32r(v.x - h.x), tf32r(v.y - h.y),
                                   tf32r(v.z - h.z), tf32r(v.w - h.w));
            *(float4*)&Kh[r * QLD + kcol] = h;
            *(float4*)&Kl[r * QLD + kcol] = l;
        }
        // store cD tile (tf32-rounded, rows >= WA_ already zero)
#pragma unroll
        for (int it = 0; it < 5; ++it) {
            const int n = (tid >> 4) + it * 16;
            if (n < NP) *(float4*)&CDs[n * CLD + ccol] = tf32r4(creg[it]);
        }
        __syncthreads();
        // prefetch next tile
        if (kc + 1 < S_ / KT) {
            const size_t krow0 = (size_t)bh * S_ + (kc + 1) * KT;
#pragma unroll
            for (int p = 0; p < 8; ++p) {
                const int r = (tid >> 5) + p * 8;
                kreg[p] = *(const float4*)(g_k + (krow0 + r) * DK_ + kcol);
            }
#pragma unroll
            for (int it = 0; it < 5; ++it) {
                const int n = (tid >> 4) + it * 16;
                creg[it] = (n < WA_)
                    ? *(const float4*)(g_cDT + ((size_t)bh * WA_ + n) * S_ + (kc + 1) * KT + ccol)
                    : make_float4(0.f, 0.f, 0.f, 0.f);
            }
        }

        // ---- S-tile: 16 rows x 64 cols per warp, split-tf32 ----
        float sacc[8][4] = {};
#pragma unroll
        for (int k8 = 0; k8 < DK_; k8 += 8) {
            const int o = arow * QLD + q4 + k8;
            const float f0 = Qs[o], f1 = Qs[o + 8 * QLD];
            const float f2 = Qs[o + 4], f3 = Qs[o + 8 * QLD + 4];
            const float ah0 = tf32r(f0), ah1 = tf32r(f1), ah2 = tf32r(f2), ah3 = tf32r(f3);
            const float al0 = tf32r(f0 - ah0), al1 = tf32r(f1 - ah1);
            const float al2 = tf32r(f2 - ah2), al3 = tf32r(f3 - ah3);
#pragma unroll
            for (int j = 0; j < 8; ++j) {
                const int ob = (8 * j + grp) * QLD + q4 + k8;
                const float bh0 = Kh[ob], bh1 = Kh[ob + 4];
                const float bl0 = Kl[ob], bl1 = Kl[ob + 4];
                mma8(sacc[j], ah0, ah1, ah2, ah3, bh0, bh1);
                mma8(sacc[j], ah0, ah1, ah2, ah3, bl0, bl1);
                mma8(sacc[j], al0, al1, al2, al3, bh0, bh1);
            }
        }

        // ---- online softmax (warp-local; rows grp and grp+8) ----
        float tm0 = sacc[0][0], tm1 = sacc[0][2];
#pragma unroll
        for (int j = 0; j < 8; ++j) {
            tm0 = fmaxf(tm0, fmaxf(sacc[j][0], sacc[j][1]));
            tm1 = fmaxf(tm1, fmaxf(sacc[j][2], sacc[j][3]));
        }
        tm0 = fmaxf(tm0, __shfl_xor_sync(0xFFFFFFFFu, tm0, 1));
        tm0 = fmaxf(tm0, __shfl_xor_sync(0xFFFFFFFFu, tm0, 2));
        tm1 = fmaxf(tm1, __shfl_xor_sync(0xFFFFFFFFu, tm1, 1));
        tm1 = fmaxf(tm1, __shfl_xor_sync(0xFFFFFFFFu, tm1, 2));
        const float mn0 = fmaxf(m0v, tm0), mn1 = fmaxf(m1v, tm1);
        const float a0s = __expf(m0v - mn0), a1s = __expf(m1v - mn1);

        float ts0 = 0.f, ts1 = 0.f;
#pragma unroll
        for (int j = 0; j < 8; ++j) {
            const float p0 = __expf(sacc[j][0] - mn0);
            const float p1 = __expf(sacc[j][1] - mn0);
            const float p2 = __expf(sacc[j][2] - mn1);
            const float p3 = __expf(sacc[j][3] - mn1);
            ts0 += p0 + p1; ts1 += p2 + p3;
            *(float2*)&Pw[grp * CLD + 8 * j + 2 * q4] = make_float2(tf32r(p0), tf32r(p1));
            *(float2*)&Pw[(grp + 8) * CLD + 8 * j + 2 * q4] = make_float2(tf32r(p2), tf32r(p3));
        }
        ts0 += __shfl_xor_sync(0xFFFFFFFFu, ts0, 1);
        ts0 += __shfl_xor_sync(0xFFFFFFFFu, ts0, 2);
        ts1 += __shfl_xor_sync(0xFFFFFFFFu, ts1, 1);
        ts1 += __shfl_xor_sync(0xFFFFFFFFu, ts1, 2);
        l0 = l0 * a0s + ts0;
        l1 = l1 * a1s + ts1;
        m0v = mn0; m1v = mn1;
#pragma unroll
        for (int n = 0; n < 9; ++n) {
            oacc[n][0] *= a0s; oacc[n][1] *= a0s;
            oacc[n][2] *= a1s; oacc[n][3] *= a1s;
        }
        __syncwarp();

        // ---- O += P @ cD^T  (warp rows x 72 padded wavelet cols) ----
#pragma unroll
        for (int k8 = 0; k8 < KT; k8 += 8) {
            const int o = grp * CLD + q4 + k8;
            const float a0 = Pw[o], a1 = Pw[o + 8 * CLD];
            const float a2 = Pw[o + 4], a3 = Pw[o + 8 * CLD + 4];
#pragma unroll
            for (int n = 0; n < 9; ++n) {
                const int ob = (8 * n + grp) * CLD + q4 + k8;
                mma8(oacc[n], a0, a1, a2, a3, CDs[ob], CDs[ob + 4]);
            }
        }
        __syncwarp();
    }

    // ---- epilogue: normalize and store ----
    const int bb = bh >> 3, hh = bh & 7;
    const float i0 = 1.0f / l0, i1 = 1.0f / l1;
    const int s0 = q0 + wid * 16 + grp, s1 = s0 + 8;
    float* o0 = out1 + (size_t)(bb * S_ + s0) * OUT1W_ + hh * WA_;
    float* o1 = out1 + (size_t)(bb * S_ + s1) * OUT1W_ + hh * WA_;
#pragma unroll
    for (int n = 0; n < 9; ++n) {
        const int c = 8 * n + 2 * q4;
        if (c < WA_)     { o0[c]     = oacc[n][0] * i0; o1[c]     = oacc[n][2] * i1; }
        if (c + 1 < WA_) { o0[c + 1] = oacc[n][1] * i0; o1[c + 1] = oacc[n][3] * i1; }
    }
}

// =====================================================================
extern "C" void kernel_launch(void* const* d_in, const int* in_sizes, int n_in,
                              void* d_out, int out_size)
{
    const float* x  = (const float*)d_in[0];
    const float* Wq = (const float*)d_in[1];
    const float* Wk = (const float*)d_in[2];
    const float* Wv = (const float*)d_in[3];

    float* out1 = (float*)d_out;
    float* out2 = out1 + (size_t)out_size / 2;

    cudaFuncSetAttribute(qkv_gemm,   cudaFuncAttributeMaxDynamicSharedMemorySize, (int)SMEM_QKV);
    cudaFuncSetAttribute(fused_attn, cudaFuncAttributeMaxDynamicSharedMemorySize, (int)SMEM_FUSED);

    qkv_gemm  <<<dim3(HD_ / 64, (B_ * S_) / 128, 3), 256, SMEM_QKV>>>(x, Wq, Wk, Wv);
    dwt_kernel<<<BH_ * S_, 128>>>(out2);
    fused_attn<<<dim3(S_ / 128, BH_), 256, SMEM_FUSED>>>(out1);
}